// round 9
// baseline (speedup 1.0000x reference)
#include <cuda_runtime.h>
#include <cuda_fp16.h>
#include <math.h>

#define N0 8192
#define N1 4096
#define N2 8192
// W0: [N0, N1] row-major, W1: [N1, N2] row-major

#define CHUNK_BYTES 65536
#define NBUF 3
#define SMEM_DYN (NBUF * CHUNK_BYTES)

// Persistent state (device globals — allocation-free scratch)
__device__ float g_x1[N1];
__device__ float g_x2[N2];
__device__ float g_e1[N1];
__device__ float g_g1[N1];
__device__ float g_g2[N2];
__device__ int   g_ctr;
// fp16 weight copies (written once in step 1, read in steps 2..9 + final)
__device__ __half g_W0h[(size_t)N0 * N1];   // 64 MB
__device__ __half g_W1h[(size_t)N1 * N2];   // 64 MB

__device__ __forceinline__ float dot4(float4 a, float4 b) {
    return a.x * b.x + a.y * b.y + a.z * b.z + a.w * b.w;
}
// dot of 8 halfs (uint4) with 8 floats, fp32 accumulate
__device__ __forceinline__ float dot8(uint4 w, const float* x) {
    const __half2* h = (const __half2*)&w;
    float s = 0.f;
#pragma unroll
    for (int j = 0; j < 4; j++) {
        float2 v = __half22float2(h[j]);
        s += v.x * x[2 * j] + v.y * x[2 * j + 1];
    }
    return s;
}
// a[0..8) += e * w
__device__ __forceinline__ void axpy8(uint4 w, float e, float* a) {
    const __half2* h = (const __half2*)&w;
#pragma unroll
    for (int j = 0; j < 4; j++) {
        float2 v = __half22float2(h[j]);
        a[2 * j]     += e * v.x;
        a[2 * j + 1] += e * v.y;
    }
}
__device__ __forceinline__ uint2 f4_to_h4(float4 v) {
    __half2 a = __floats2half2_rn(v.x, v.y);
    __half2 b = __floats2half2_rn(v.z, v.w);
    uint2 u;
    u.x = *(unsigned*)&a;
    u.y = *(unsigned*)&b;
    return u;
}

// ---------------------------------------------------------------------------
__global__ void k_init(float* __restrict__ out) {
    int i = blockIdx.x * blockDim.x + threadIdx.x;
    if (i < N1) { g_x1[i] = 0.f; g_g1[i] = 0.f; g_e1[i] = 0.f; }
    if (i < N2) { g_x2[i] = 0.f; g_g2[i] = 0.f; }
    if (i == 0) { out[0] = 0.f; g_ctr = 0; }
}

// ---------------------------------------------------------------------------
// Fused state update by the LAST block (threadfence-reduction pattern).
// ---------------------------------------------------------------------------
__device__ __forceinline__ void step_epilogue(int nblocks) {
    __shared__ int is_last;
    __threadfence();
    if (threadIdx.x == 0) {
        int v = atomicAdd(&g_ctr, 1);
        is_last = (v == nblocks - 1);
    }
    __syncthreads();
    if (!is_last) return;
    __threadfence();
    const int tid = threadIdx.x;
    const int nt  = blockDim.x;
    for (int i = tid; i < N1; i += nt) {
        float gr = fminf(fmaxf(-g_e1[i] + g_g1[i], -1.f), 1.f);
        g_x1[i] = tanhf(g_x1[i] + 0.01f * gr);
        g_g1[i] = 0.f;
    }
    for (int i = tid; i < N2; i += nt) {
        float x2 = g_x2[i];
        float gr = fminf(fmaxf(-x2 + g_g2[i], -1.f), 1.f);
        g_x2[i] = tanhf(x2 + 0.01f * gr);
        g_g2[i] = 0.f;
    }
    if (tid == 0) g_ctr = 0;
}

// ---------------------------------------------------------------------------
// Step 1: fp32 fused step (W read once) + write fp16 copies + fused update.
// Blocks [0,128): W0 (64 rows). Blocks [128,256): W1 (32 rows). 512 threads.
// (Round-3 geometry — proven.)
// ---------------------------------------------------------------------------
__global__ void __launch_bounds__(512) k_step1(const float* __restrict__ x0,
                                               const float* __restrict__ W0,
                                               const float* __restrict__ W1) {
    __shared__ float sp[8][16];
    __shared__ float se[8];
    const int tid  = threadIdx.x;
    const int warp = tid >> 5;
    const int lane = tid & 31;

    if (blockIdx.x < 128) {
        const int rowBase = blockIdx.x * 64;
        const float4* xv = (const float4*)g_x1;
        const float4 xA = xv[tid];
        const float4 xB = xv[tid + 512];
        float4 accA = make_float4(0, 0, 0, 0);
        float4 accB = make_float4(0, 0, 0, 0);

        #pragma unroll 1
        for (int t = 0; t < 8; t++) {
            const int rb = rowBase + t * 8;
            const float4* base = (const float4*)W0 + (size_t)rb * 1024 + tid;
            float4 wA[8], wB[8];
            #pragma unroll
            for (int r = 0; r < 8; r++) {
                wA[r] = base[(size_t)r * 1024];
                wB[r] = base[(size_t)r * 1024 + 512];
            }
            #pragma unroll
            for (int r = 0; r < 8; r++) {
                uint2* dst = (uint2*)g_W0h + (size_t)(rb + r) * 1024;
                dst[tid]       = f4_to_h4(wA[r]);
                dst[tid + 512] = f4_to_h4(wB[r]);
            }
            #pragma unroll
            for (int r = 0; r < 8; r++) {
                float p = dot4(wA[r], xA) + dot4(wB[r], xB);
                #pragma unroll
                for (int o = 16; o; o >>= 1) p += __shfl_xor_sync(0xFFFFFFFFu, p, o);
                if (lane == 0) sp[r][warp] = p;
            }
            __syncthreads();
            if (tid < 8) {
                float s = 0.f;
                #pragma unroll
                for (int w = 0; w < 16; w++) s += sp[tid][w];
                se[tid] = x0[rb + tid] - tanhf(s);
            }
            __syncthreads();
            #pragma unroll
            for (int r = 0; r < 8; r++) {
                const float e = se[r];
                accA.x += e * wA[r].x;  accA.y += e * wA[r].y;
                accA.z += e * wA[r].z;  accA.w += e * wA[r].w;
                accB.x += e * wB[r].x;  accB.y += e * wB[r].y;
                accB.z += e * wB[r].z;  accB.w += e * wB[r].w;
            }
        }
        const int cA = 4 * tid;
        const int cB = 4 * (tid + 512);
        atomicAdd(&g_g1[cA + 0], accA.x);
        atomicAdd(&g_g1[cA + 1], accA.y);
        atomicAdd(&g_g1[cA + 2], accA.z);
        atomicAdd(&g_g1[cA + 3], accA.w);
        atomicAdd(&g_g1[cB + 0], accB.x);
        atomicAdd(&g_g1[cB + 1], accB.y);
        atomicAdd(&g_g1[cB + 2], accB.z);
        atomicAdd(&g_g1[cB + 3], accB.w);
    } else {
        const int rowBase = (blockIdx.x - 128) * 32;
        const float4* xv = (const float4*)g_x2;
        float4 xC[4];
        #pragma unroll
        for (int k = 0; k < 4; k++) xC[k] = xv[tid + k * 512];
        float4 acc[4] = {make_float4(0,0,0,0), make_float4(0,0,0,0),
                         make_float4(0,0,0,0), make_float4(0,0,0,0)};

        #pragma unroll 1
        for (int t = 0; t < 8; t++) {
            const int rb = rowBase + t * 4;
            const float4* base = (const float4*)W1 + (size_t)rb * 2048 + tid;
            float4 w[4][4];
            #pragma unroll
            for (int r = 0; r < 4; r++)
                #pragma unroll
                for (int k = 0; k < 4; k++)
                    w[r][k] = base[(size_t)r * 2048 + k * 512];
            #pragma unroll
            for (int r = 0; r < 4; r++) {
                uint2* dst = (uint2*)g_W1h + (size_t)(rb + r) * 2048;
                #pragma unroll
                for (int k = 0; k < 4; k++)
                    dst[tid + k * 512] = f4_to_h4(w[r][k]);
            }
            #pragma unroll
            for (int r = 0; r < 4; r++) {
                float p = dot4(w[r][0], xC[0]) + dot4(w[r][1], xC[1])
                        + dot4(w[r][2], xC[2]) + dot4(w[r][3], xC[3]);
                #pragma unroll
                for (int o = 16; o; o >>= 1) p += __shfl_xor_sync(0xFFFFFFFFu, p, o);
                if (lane == 0) sp[r][warp] = p;
            }
            __syncthreads();
            if (tid < 4) {
                float s = 0.f;
                #pragma unroll
                for (int wi = 0; wi < 16; wi++) s += sp[tid][wi];
                float e = g_x1[rb + tid] - tanhf(s);
                se[tid] = e;
                g_e1[rb + tid] = e;
            }
            __syncthreads();
            #pragma unroll
            for (int r = 0; r < 4; r++) {
                const float e = se[r];
                #pragma unroll
                for (int k = 0; k < 4; k++) {
                    acc[k].x += e * w[r][k].x;  acc[k].y += e * w[r][k].y;
                    acc[k].z += e * w[r][k].z;  acc[k].w += e * w[r][k].w;
                }
            }
        }
        #pragma unroll
        for (int k = 0; k < 4; k++) {
            const int c = 4 * (tid + k * 512);
            atomicAdd(&g_g2[c + 0], acc[k].x);
            atomicAdd(&g_g2[c + 1], acc[k].y);
            atomicAdd(&g_g2[c + 2], acc[k].z);
            atomicAdd(&g_g2[c + 3], acc[k].w);
        }
    }
    step_epilogue(256);
}

// ---------------------------------------------------------------------------
// cp.async: issue one 64 KB chunk (chunk id 0..15) into smem ring buffer.
// id 0..7  -> W0h rows [rowBase0 + id*8,   +8)  (8 rows x 8 KB)
// id 8..15 -> W1h rows [rowBase1 + (id-8)*4, +4) (4 rows x 16 KB)
// 512 threads x 8 x 16B = 64 KB. Thread tid copies uint4 indices tid + k*512,
// which are exactly the elements it later reads -> per-thread wait suffices.
// ---------------------------------------------------------------------------
__device__ __forceinline__ void issue_chunk(int id, char* sbase,
                                            int rowBase0, int rowBase1, int tid) {
    if (id >= 16) return;
    const char* src;
    if (id < 8)
        src = (const char*)(g_W0h + (size_t)(rowBase0 + id * 8) * N1);
    else
        src = (const char*)(g_W1h + (size_t)(rowBase1 + (id - 8) * 4) * N2);
    unsigned dst = (unsigned)__cvta_generic_to_shared(sbase + (id % NBUF) * CHUNK_BYTES)
                 + tid * 16;
    src += tid * 16;
    #pragma unroll
    for (int k = 0; k < 8; k++)
        asm volatile("cp.async.cg.shared.global [%0], [%1], 16;"
                     :: "r"(dst + k * 8192), "l"(src + (size_t)k * 8192) : "memory");
    asm volatile("cp.async.commit_group;" ::: "memory");
}

// ---------------------------------------------------------------------------
// Steps 2..9: fp16 fused step, cp.async smem-staged.
// grid 128 x 512 thr. Block: W0 rows [b*64,+64) then W1 rows [b*32,+32),
// streamed as 16 x 64 KB chunks through a 3-buffer smem ring (~128 KB of
// copies in flight at all times, independent of registers/barriers).
// Per chunk: cache own uint4 slice in regs, dot -> block reduce -> axpy.
// ---------------------------------------------------------------------------
__global__ void __launch_bounds__(512) k_step_h(const float* __restrict__ x0) {
    extern __shared__ char sbuf[];
    __shared__ float sp[8][16];
    __shared__ float se[8];
    const int tid  = threadIdx.x;
    const int warp = tid >> 5;
    const int lane = tid & 31;
    const int rowBase0 = blockIdx.x * 64;
    const int rowBase1 = blockIdx.x * 32;

    // prologue: 3 chunks in flight
    issue_chunk(0, sbuf, rowBase0, rowBase1, tid);
    issue_chunk(1, sbuf, rowBase0, rowBase1, tid);
    issue_chunk(2, sbuf, rowBase0, rowBase1, tid);

    // ------------------ W0 half: 8 chunks x 8 rows ------------------
    {
        float xf[8];
        {
            const float4* xv = (const float4*)g_x1;
            float4 a = xv[2 * tid], b = xv[2 * tid + 1];
            xf[0]=a.x; xf[1]=a.y; xf[2]=a.z; xf[3]=a.w;
            xf[4]=b.x; xf[5]=b.y; xf[6]=b.z; xf[7]=b.w;
        }
        float acc[8];
        #pragma unroll
        for (int j = 0; j < 8; j++) acc[j] = 0.f;

        #pragma unroll 1
        for (int t = 0; t < 8; t++) {
            asm volatile("cp.async.wait_group 2;" ::: "memory");
            const uint4* buf = (const uint4*)(sbuf + (t % NBUF) * CHUNK_BYTES);
            uint4 w[8];
            #pragma unroll
            for (int r = 0; r < 8; r++) w[r] = buf[r * 512 + tid];
            #pragma unroll
            for (int r = 0; r < 8; r++) {
                float p = dot8(w[r], xf);
                #pragma unroll
                for (int o = 16; o; o >>= 1) p += __shfl_xor_sync(0xFFFFFFFFu, p, o);
                if (lane == 0) sp[r][warp] = p;
            }
            __syncthreads();              // everyone cached w + sp complete
            issue_chunk(t + 3, sbuf, rowBase0, rowBase1, tid);  // buffer freed
            if (tid < 128) {
                const int r = tid >> 4, wi = tid & 15;
                float v = sp[r][wi];
                v += __shfl_xor_sync(0xFFFFFFFFu, v, 8);
                v += __shfl_xor_sync(0xFFFFFFFFu, v, 4);
                v += __shfl_xor_sync(0xFFFFFFFFu, v, 2);
                v += __shfl_xor_sync(0xFFFFFFFFu, v, 1);
                if (wi == 0) se[r] = x0[rowBase0 + t * 8 + r] - tanhf(v);
            }
            __syncthreads();
            #pragma unroll
            for (int r = 0; r < 8; r++) axpy8(w[r], se[r], acc);
        }
        #pragma unroll
        for (int j = 0; j < 8; j++) atomicAdd(&g_g1[8 * tid + j], acc[j]);
    }

    // ------------------ W1 half: 8 chunks x 4 rows ------------------
    {
        float xgA[8], xgB[8];
        {
            const float4* xv = (const float4*)g_x2;
            float4 a = xv[2 * tid],         b = xv[2 * tid + 1];
            float4 c = xv[2 * (tid + 512)], d = xv[2 * (tid + 512) + 1];
            xgA[0]=a.x; xgA[1]=a.y; xgA[2]=a.z; xgA[3]=a.w;
            xgA[4]=b.x; xgA[5]=b.y; xgA[6]=b.z; xgA[7]=b.w;
            xgB[0]=c.x; xgB[1]=c.y; xgB[2]=c.z; xgB[3]=c.w;
            xgB[4]=d.x; xgB[5]=d.y; xgB[6]=d.z; xgB[7]=d.w;
        }
        float accA[8], accB[8];
        #pragma unroll
        for (int j = 0; j < 8; j++) { accA[j] = 0.f; accB[j] = 0.f; }

        #pragma unroll 1
        for (int t = 8; t < 16; t++) {
            asm volatile("cp.async.wait_group 2;" ::: "memory");
            const uint4* buf = (const uint4*)(sbuf + (t % NBUF) * CHUNK_BYTES);
            uint4 wA[4], wB[4];
            #pragma unroll
            for (int r = 0; r < 4; r++) {
                wA[r] = buf[r * 1024 + tid];
                wB[r] = buf[r * 1024 + 512 + tid];
            }
            #pragma unroll
            for (int r = 0; r < 4; r++) {
                float p = dot8(wA[r], xgA) + dot8(wB[r], xgB);
                #pragma unroll
                for (int o = 16; o; o >>= 1) p += __shfl_xor_sync(0xFFFFFFFFu, p, o);
                if (lane == 0) sp[r][warp] = p;
            }
            __syncthreads();
            issue_chunk(t + 3, sbuf, rowBase0, rowBase1, tid);
            if (tid < 64) {
                const int r = tid >> 4, wi = tid & 15;
                float v = sp[r][wi];
                v += __shfl_xor_sync(0xFFFFFFFFu, v, 8);
                v += __shfl_xor_sync(0xFFFFFFFFu, v, 4);
                v += __shfl_xor_sync(0xFFFFFFFFu, v, 2);
                v += __shfl_xor_sync(0xFFFFFFFFu, v, 1);
                if (wi == 0) {
                    const int row = rowBase1 + (t - 8) * 4 + r;
                    float e = g_x1[row] - tanhf(v);
                    se[r] = e;
                    g_e1[row] = e;
                }
            }
            __syncthreads();
            #pragma unroll
            for (int r = 0; r < 4; r++) {
                axpy8(wA[r], se[r], accA);
                axpy8(wB[r], se[r], accB);
            }
        }
        #pragma unroll
        for (int j = 0; j < 8; j++) atomicAdd(&g_g2[8 * tid + j], accA[j]);
        #pragma unroll
        for (int j = 0; j < 8; j++) atomicAdd(&g_g2[8 * (tid + 512) + j], accB[j]);
    }

    step_epilogue(128);
}

// ---------------------------------------------------------------------------
// Final: err = ||x0 - tanh(W0@x1)||^2 + ||x1 - tanh(W1@x2)||^2 + ||x2||^2
// fp16 weights, warp-per-row.
// ---------------------------------------------------------------------------
__global__ void __launch_bounds__(256) k_final_h(const float* __restrict__ x0,
                                                 float* __restrict__ out) {
    __shared__ float s_part[8];
    const int warpInBlock = threadIdx.x >> 5;
    const int warp = (blockIdx.x * blockDim.x + threadIdx.x) >> 5;
    const int lane = threadIdx.x & 31;

    float local = 0.f;
    if (warp < N0) {
        const uint4* row = (const uint4*)g_W0h + (size_t)warp * 512;
        const float4* xv = (const float4*)g_x1;
        float acc = 0.f;
        #pragma unroll 4
        for (int i = lane; i < 512; i += 32) {
            uint4 w = row[i];
            float4 a = xv[2 * i], b = xv[2 * i + 1];
            float xf[8] = {a.x, a.y, a.z, a.w, b.x, b.y, b.z, b.w};
            acc += dot8(w, xf);
        }
        #pragma unroll
        for (int o = 16; o; o >>= 1) acc += __shfl_xor_sync(0xFFFFFFFFu, acc, o);
        if (lane == 0) {
            float e = x0[warp] - tanhf(acc);
            float x2v = g_x2[warp];
            local = e * e + x2v * x2v;
        }
    } else {
        const int r = warp - N0;
        const uint4* row = (const uint4*)g_W1h + (size_t)r * 1024;
        const float4* xv = (const float4*)g_x2;
        float acc = 0.f;
        #pragma unroll 4
        for (int i = lane; i < 1024; i += 32) {
            uint4 w = row[i];
            float4 a = xv[2 * i], b = xv[2 * i + 1];
            float xf[8] = {a.x, a.y, a.z, a.w, b.x, b.y, b.z, b.w};
            acc += dot8(w, xf);
        }
        #pragma unroll
        for (int o = 16; o; o >>= 1) acc += __shfl_xor_sync(0xFFFFFFFFu, acc, o);
        if (lane == 0) {
            float e = g_x1[r] - tanhf(acc);
            local = e * e;
        }
    }

    if (lane == 0) s_part[warpInBlock] = local;
    __syncthreads();
    if (threadIdx.x == 0) {
        float s = 0.f;
        #pragma unroll
        for (int w = 0; w < 8; w++) s += s_part[w];
        atomicAdd(out, s);
    }
}

// ---------------------------------------------------------------------------
extern "C" void kernel_launch(void* const* d_in, const int* in_sizes, int n_in,
                              void* d_out, int out_size) {
    const float* x0 = (const float*)d_in[0];
    const float* W0 = (const float*)d_in[1];
    const float* W1 = (const float*)d_in[2];
    float* out = (float*)d_out;

    // Opt-in to >48KB dynamic smem (idempotent; persists per-context).
    cudaFuncSetAttribute(k_step_h, cudaFuncAttributeMaxDynamicSharedMemorySize,
                         SMEM_DYN);

    k_init<<<32, 256>>>(out);
    k_step1<<<256, 512>>>(x0, W0, W1);              // fp32 step + fp16 convert
    for (int s = 0; s < 8; s++)
        k_step_h<<<128, 512, SMEM_DYN>>>(x0);       // fp16 cp.async steps
    k_final_h<<<(N0 + N1) / 8, 256>>>(x0, out);     // fp16 final error
}

// round 10
// speedup vs baseline: 1.2663x; 1.2663x over previous
#include <cuda_runtime.h>
#include <math.h>

#define N0 8192
#define N1 4096
#define N2 8192
// W0: [N0, N1] row-major, W1: [N1, N2] row-major

// Persistent state (device globals — allocation-free scratch)
__device__ float g_x1[N1];
__device__ float g_x2[N2];
__device__ float g_e1[N1];
__device__ float g_g1[N1];
__device__ float g_g2[N2];
__device__ int   g_ctr;

__device__ __forceinline__ float dot4(float4 a, float4 b) {
    return a.x * b.x + a.y * b.y + a.z * b.z + a.w * b.w;
}

// ---------------------------------------------------------------------------
__global__ void k_init(float* __restrict__ out) {
    int i = blockIdx.x * blockDim.x + threadIdx.x;
    if (i < N1) { g_x1[i] = 0.f; g_g1[i] = 0.f; g_e1[i] = 0.f; }
    if (i < N2) { g_x2[i] = 0.f; g_g2[i] = 0.f; }
    if (i == 0) { out[0] = 0.f; g_ctr = 0; }
}

// ---------------------------------------------------------------------------
// Fused state update by the LAST block (threadfence-reduction pattern).
// x1 <- tanh(x1 + .01 clip(-e1 + g1)); x2 <- tanh(x2 + .01 clip(-x2 + g2)).
// Zeroes grads, resets counter.
// ---------------------------------------------------------------------------
__device__ __forceinline__ void step_epilogue(int nblocks) {
    __shared__ int is_last;
    __threadfence();
    if (threadIdx.x == 0) {
        int v = atomicAdd(&g_ctr, 1);
        is_last = (v == nblocks - 1);
    }
    __syncthreads();
    if (!is_last) return;
    __threadfence();
    const int tid = threadIdx.x;
    const int nt  = blockDim.x;
    for (int i = tid; i < N1; i += nt) {
        float gr = fminf(fmaxf(-g_e1[i] + g_g1[i], -1.f), 1.f);
        g_x1[i] = tanhf(g_x1[i] + 0.01f * gr);
        g_g1[i] = 0.f;
    }
    for (int i = tid; i < N2; i += nt) {
        float x2 = g_x2[i];
        float gr = fminf(fmaxf(-x2 + g_g2[i], -1.f), 1.f);
        g_x2[i] = tanhf(x2 + 0.01f * gr);
        g_g2[i] = 0.f;
    }
    if (tid == 0) g_ctr = 0;
}

// ---------------------------------------------------------------------------
// Step 1 specialized: x1 = x2 = 0  =>  e0 = x0, e1 = 0, g2 = 0.
// Only work: g1 = W0^T x0 (pure streaming axpy, no dots, no barriers),
// then the generic epilogue (e1 = 0, g2 = 0 give the right update).
// grid 128 x 512: block streams rows [b*64, b*64+64).
// ---------------------------------------------------------------------------
__global__ void __launch_bounds__(512) k_step1(const float* __restrict__ x0,
                                               const float* __restrict__ W0) {
    const int tid = threadIdx.x;
    const int rowBase = blockIdx.x * 64;
    float4 accA = make_float4(0, 0, 0, 0);
    float4 accB = make_float4(0, 0, 0, 0);

    #pragma unroll 1
    for (int t = 0; t < 8; t++) {
        const int rb = rowBase + t * 8;
        const float4* base = (const float4*)W0 + (size_t)rb * 1024 + tid;
        float4 wA[8], wB[8];
        #pragma unroll
        for (int r = 0; r < 8; r++) {
            wA[r] = base[(size_t)r * 1024];
            wB[r] = base[(size_t)r * 1024 + 512];
        }
        #pragma unroll
        for (int r = 0; r < 8; r++) {
            const float e = __ldg(x0 + rb + r);
            accA.x += e * wA[r].x;  accA.y += e * wA[r].y;
            accA.z += e * wA[r].z;  accA.w += e * wA[r].w;
            accB.x += e * wB[r].x;  accB.y += e * wB[r].y;
            accB.z += e * wB[r].z;  accB.w += e * wB[r].w;
        }
    }
    const int cA = 4 * tid;
    const int cB = 4 * (tid + 512);
    atomicAdd(&g_g1[cA + 0], accA.x);
    atomicAdd(&g_g1[cA + 1], accA.y);
    atomicAdd(&g_g1[cA + 2], accA.z);
    atomicAdd(&g_g1[cA + 3], accA.w);
    atomicAdd(&g_g1[cB + 0], accB.x);
    atomicAdd(&g_g1[cB + 1], accB.y);
    atomicAdd(&g_g1[cB + 2], accB.z);
    atomicAdd(&g_g1[cB + 3], accB.w);
    step_epilogue(128);
}

// ---------------------------------------------------------------------------
// Steps 2..9: fp32 fused step, single wave (grid 128), double-buffered.
// Block: W0 rows [b*64,+64) as 16 tiles x 4 rows (2 float4/row/thread),
// then W1 rows [b*32,+32) as 16 tiles x 2 rows (4 float4/row/thread).
// Next tile's 8 LDG.128 issue BEFORE the current tile's reduce/barriers.
// Live regs ~115 < 128 cap: no spill.
// ---------------------------------------------------------------------------
__global__ void __launch_bounds__(512) k_step(const float* __restrict__ x0,
                                              const float* __restrict__ W0,
                                              const float* __restrict__ W1) {
    __shared__ float sp[4][16];
    __shared__ float se[4];
    const int tid  = threadIdx.x;
    const int warp = tid >> 5;
    const int lane = tid & 31;

    // ------------------ W0 section: [8192 x 4096] ------------------
    {
        const int rowBase = blockIdx.x * 64;
        const float4* Wb = (const float4*)W0;
        const float4* xv = (const float4*)g_x1;
        const float4 xA = xv[tid];
        const float4 xB = xv[tid + 512];
        float4 accA = make_float4(0, 0, 0, 0);
        float4 accB = make_float4(0, 0, 0, 0);

        float4 w[2][8];
        #pragma unroll
        for (int r = 0; r < 4; r++) {
            w[0][2*r]   = Wb[(size_t)(rowBase + r) * 1024 + tid];
            w[0][2*r+1] = Wb[(size_t)(rowBase + r) * 1024 + tid + 512];
        }
        #pragma unroll 2
        for (int t = 0; t < 16; t++) {
            const int cur = t & 1, nxt = cur ^ 1;
            const int rb = rowBase + t * 4;
            if (t < 15) {
                #pragma unroll
                for (int r = 0; r < 4; r++) {
                    w[nxt][2*r]   = Wb[(size_t)(rb + 4 + r) * 1024 + tid];
                    w[nxt][2*r+1] = Wb[(size_t)(rb + 4 + r) * 1024 + tid + 512];
                }
            }
            #pragma unroll
            for (int r = 0; r < 4; r++) {
                float p = dot4(w[cur][2*r], xA) + dot4(w[cur][2*r+1], xB);
                #pragma unroll
                for (int o = 16; o; o >>= 1) p += __shfl_xor_sync(0xFFFFFFFFu, p, o);
                if (lane == 0) sp[r][warp] = p;
            }
            __syncthreads();
            if (tid < 64) {
                const int r = tid >> 4, wi = tid & 15;
                float v = sp[r][wi];
                v += __shfl_xor_sync(0xFFFFFFFFu, v, 8);
                v += __shfl_xor_sync(0xFFFFFFFFu, v, 4);
                v += __shfl_xor_sync(0xFFFFFFFFu, v, 2);
                v += __shfl_xor_sync(0xFFFFFFFFu, v, 1);
                if (wi == 0) se[r] = __ldg(x0 + rb + r) - tanhf(v);
            }
            __syncthreads();
            #pragma unroll
            for (int r = 0; r < 4; r++) {
                const float e = se[r];
                accA.x += e * w[cur][2*r].x;    accA.y += e * w[cur][2*r].y;
                accA.z += e * w[cur][2*r].z;    accA.w += e * w[cur][2*r].w;
                accB.x += e * w[cur][2*r+1].x;  accB.y += e * w[cur][2*r+1].y;
                accB.z += e * w[cur][2*r+1].z;  accB.w += e * w[cur][2*r+1].w;
            }
        }
        const int cA = 4 * tid;
        const int cB = 4 * (tid + 512);
        atomicAdd(&g_g1[cA + 0], accA.x);
        atomicAdd(&g_g1[cA + 1], accA.y);
        atomicAdd(&g_g1[cA + 2], accA.z);
        atomicAdd(&g_g1[cA + 3], accA.w);
        atomicAdd(&g_g1[cB + 0], accB.x);
        atomicAdd(&g_g1[cB + 1], accB.y);
        atomicAdd(&g_g1[cB + 2], accB.z);
        atomicAdd(&g_g1[cB + 3], accB.w);
    }

    // ------------------ W1 section: [4096 x 8192] ------------------
    {
        const int rowBase = blockIdx.x * 32;
        const float4* Wb = (const float4*)W1;
        const float4* xv = (const float4*)g_x2;
        float4 xC[4];
        #pragma unroll
        for (int k = 0; k < 4; k++) xC[k] = xv[tid + k * 512];
        float4 acc[4] = {make_float4(0,0,0,0), make_float4(0,0,0,0),
                         make_float4(0,0,0,0), make_float4(0,0,0,0)};

        float4 w[2][8];
        #pragma unroll
        for (int r = 0; r < 2; r++)
            #pragma unroll
            for (int k = 0; k < 4; k++)
                w[0][4*r+k] = Wb[(size_t)(rowBase + r) * 2048 + tid + k * 512];

        #pragma unroll 2
        for (int t = 0; t < 16; t++) {
            const int cur = t & 1, nxt = cur ^ 1;
            const int rb = rowBase + t * 2;
            if (t < 15) {
                #pragma unroll
                for (int r = 0; r < 2; r++)
                    #pragma unroll
                    for (int k = 0; k < 4; k++)
                        w[nxt][4*r+k] = Wb[(size_t)(rb + 2 + r) * 2048 + tid + k * 512];
            }
            #pragma unroll
            for (int r = 0; r < 2; r++) {
                float p = dot4(w[cur][4*r],   xC[0]) + dot4(w[cur][4*r+1], xC[1])
                        + dot4(w[cur][4*r+2], xC[2]) + dot4(w[cur][4*r+3], xC[3]);
                #pragma unroll
                for (int o = 16; o; o >>= 1) p += __shfl_xor_sync(0xFFFFFFFFu, p, o);
                if (lane == 0) sp[r][warp] = p;
            }
            __syncthreads();
            if (tid < 32) {
                const int r = tid >> 4, wi = tid & 15;
                float v = sp[r][wi];
                v += __shfl_xor_sync(0xFFFFFFFFu, v, 8);
                v += __shfl_xor_sync(0xFFFFFFFFu, v, 4);
                v += __shfl_xor_sync(0xFFFFFFFFu, v, 2);
                v += __shfl_xor_sync(0xFFFFFFFFu, v, 1);
                if (wi == 0) {
                    float e = g_x1[rb + r] - tanhf(v);
                    se[r] = e;
                    g_e1[rb + r] = e;
                }
            }
            __syncthreads();
            #pragma unroll
            for (int r = 0; r < 2; r++) {
                const float e = se[r];
                #pragma unroll
                for (int k = 0; k < 4; k++) {
                    acc[k].x += e * w[cur][4*r+k].x;
                    acc[k].y += e * w[cur][4*r+k].y;
                    acc[k].z += e * w[cur][4*r+k].z;
                    acc[k].w += e * w[cur][4*r+k].w;
                }
            }
        }
        #pragma unroll
        for (int k = 0; k < 4; k++) {
            const int c = 4 * (tid + k * 512);
            atomicAdd(&g_g2[c + 0], acc[k].x);
            atomicAdd(&g_g2[c + 1], acc[k].y);
            atomicAdd(&g_g2[c + 2], acc[k].z);
            atomicAdd(&g_g2[c + 3], acc[k].w);
        }
    }

    step_epilogue(128);
}

// ---------------------------------------------------------------------------
// Final: err = ||x0 - tanh(W0@x1)||^2 + ||x1 - tanh(W1@x2)||^2 + ||x2||^2
// fp32 originals, warp-per-row (proven round 2/3).
// ---------------------------------------------------------------------------
__global__ void __launch_bounds__(256) k_final(const float* __restrict__ x0,
                                               const float* __restrict__ W0,
                                               const float* __restrict__ W1,
                                               float* __restrict__ out) {
    __shared__ float s_part[8];
    const int warpInBlock = threadIdx.x >> 5;
    const int warp = (blockIdx.x * blockDim.x + threadIdx.x) >> 5;
    const int lane = threadIdx.x & 31;

    float local = 0.f;
    if (warp < N0) {
        const float4* row = (const float4*)(W0 + (size_t)warp * N1);
        const float4* xv  = (const float4*)g_x1;
        float acc = 0.f;
        #pragma unroll 4
        for (int i = lane; i < N1 / 4; i += 32) acc += dot4(row[i], xv[i]);
        #pragma unroll
        for (int o = 16; o; o >>= 1) acc += __shfl_xor_sync(0xFFFFFFFFu, acc, o);
        if (lane == 0) {
            float e = x0[warp] - tanhf(acc);
            float x2v = g_x2[warp];
            local = e * e + x2v * x2v;
        }
    } else {
        const int r = warp - N0;
        const float4* row = (const float4*)(W1 + (size_t)r * N2);
        const float4* xv  = (const float4*)g_x2;
        float acc = 0.f;
        #pragma unroll 4
        for (int i = lane; i < N2 / 4; i += 32) acc += dot4(row[i], xv[i]);
        #pragma unroll
        for (int o = 16; o; o >>= 1) acc += __shfl_xor_sync(0xFFFFFFFFu, acc, o);
        if (lane == 0) {
            float e = g_x1[r] - tanhf(acc);
            local = e * e;
        }
    }

    if (lane == 0) s_part[warpInBlock] = local;
    __syncthreads();
    if (threadIdx.x == 0) {
        float s = 0.f;
        #pragma unroll
        for (int w = 0; w < 8; w++) s += s_part[w];
        atomicAdd(out, s);
    }
}

// ---------------------------------------------------------------------------
extern "C" void kernel_launch(void* const* d_in, const int* in_sizes, int n_in,
                              void* d_out, int out_size) {
    const float* x0 = (const float*)d_in[0];
    const float* W0 = (const float*)d_in[1];
    const float* W1 = (const float*)d_in[2];
    float* out = (float*)d_out;

    k_init<<<32, 256>>>(out);
    k_step1<<<128, 512>>>(x0, W0);                    // specialized step 1
    for (int s = 0; s < 8; s++)
        k_step<<<128, 512>>>(x0, W0, W1);             // fp32 steps 2..9
    k_final<<<(N0 + N1) / 8, 256>>>(x0, W0, W1, out); // final error
}